// round 8
// baseline (speedup 1.0000x reference)
#include <cuda_runtime.h>
#include <math.h>

typedef unsigned long long ull;

#define BATCH 4
#define CCH   64
#define HH    256
#define WW    256
#define HW    65536
#define CMID  16
#define CIN   73
#define EPSV  1e-8f

// conv1 tile 16x16
#define TS   16
#define H20  20
#define H18  18
#define N20  400
#define N18  324
#define PPX  68
#define PPX4 17

// smem float offsets for k_conv1 (total 41044 floats = 164,176 B)
#define O_XT  0
#define O_RN  27200
#define O_ST8 27600
#define O_ST1 30192
#define O_WSX 30516
#define O_W8  39732
#define O_W1  40884
#define O_B1  41028
#define SM1F  41044

__device__ float g_xT[BATCH*HW*CCH];    // NHWC x
__device__ float g_hm[BATCH*HW*CMID];   // mid features NHWC16

// ---- packed f32x2 helpers ----
__device__ __forceinline__ void fma2(ull &d, ull a, ull b) {
    asm("fma.rn.f32x2 %0, %1, %2, %0;" : "+l"(d) : "l"(a), "l"(b));
}
__device__ __forceinline__ ull pk2(float lo, float hi) {
    ull r; asm("mov.b64 %0, {%1, %2};" : "=l"(r) : "f"(lo), "f"(hi)); return r;
}
__device__ __forceinline__ float red2(ull v) {
    float lo, hi; asm("mov.b64 {%0, %1}, %2;" : "=f"(lo), "=f"(hi) : "l"(v));
    return lo + hi;
}

// ---------------------------------------------------------------------------
// K1: NCHW -> NHWC transpose
// ---------------------------------------------------------------------------
__global__ __launch_bounds__(256) void k_transpose(const float* __restrict__ x) {
    __shared__ float s[64][65];
    int blk = blockIdx.x;
    int b   = blk >> 10;
    int p0  = (blk & 1023) << 6;
    int tid = threadIdx.x;
    const float* xb = x + b*CCH*HW;

    int pl = tid & 63;
    int c0 = tid >> 6;
#pragma unroll
    for (int i = 0; i < 16; i++) {
        int c = c0 + i*4;
        s[c][pl] = xb[c*HW + p0 + pl];
    }
    __syncthreads();

    int c4 = tid & 15;
    int pq = tid >> 4;
    float* out = g_xT + b*HW*CCH;
#pragma unroll
    for (int j = 0; j < 4; j++) {
        int p = pq + j*16;
        float4 v = make_float4(s[c4*4+0][p], s[c4*4+1][p], s[c4*4+2][p], s[c4*4+3][p]);
        reinterpret_cast<float4*>(out + (p0+p)*CCH)[c4] = v;
    }
}

// ---------------------------------------------------------------------------
// K2: fused cosine-sim + conv1 (73->16, 3x3) + leaky relu.
// 512 threads, 1 block/SM, 16x16 tile. Thread = 2 px x 4 oc. FFMA2 math.
// ---------------------------------------------------------------------------
__global__ __launch_bounds__(512, 1) void k_conv1(const float* __restrict__ w1,
                                                  const float* __restrict__ b1) {
    extern __shared__ float sm[];
    float* xt  = sm + O_XT;    // 400*68 x halo (20x20)
    float* rn  = sm + O_RN;    // 400
    float* st8 = sm + O_ST8;   // 324*8  sim k=0..7 (pair-aligned)
    float* st1 = sm + O_ST1;   // 324    sim k=8
    float* wsx = sm + O_WSX;   // 9216 x-weights
    float* ws8 = sm + O_W8;    // 9*16*8 sim-weights k<8
    float* ws1 = sm + O_W1;    // 9*16   sim-weight  k=8
    float* b1s = sm + O_B1;    // 16

    int blk = blockIdx.x;
    int b   = blk >> 8;
    int tt  = blk & 255;
    int by  = (tt >> 4) * TS, bx = (tt & 15) * TS;
    int tid = threadIdx.x;
    const float* xb = g_xT + b*HW*CCH;

    // x halo (zero OOB)
    for (int idx = tid; idx < N20*16; idx += 512) {
        int hp = idx >> 4, c4 = idx & 15;
        int hy = by + hp/H20 - 2, hx = bx + hp%H20 - 2;
        float4 v = make_float4(0.f, 0.f, 0.f, 0.f);
        if ((unsigned)hy < HH && (unsigned)hx < WW)
            v = reinterpret_cast<const float4*>(xb + (hy*WW + hx)*CCH)[c4];
        reinterpret_cast<float4*>(xt + hp*PPX)[c4] = v;
    }
    // x weights: wsx[((tp*16+c4)*16 + slot)*4 + comp], slot=j*4+og, o=(slot&3)*4+(slot>>2)
    for (int i = tid; i < 9216; i += 512) {
        int tp   = i >> 10;
        int c4   = (i >> 6) & 15;
        int slot = (i >> 2) & 15;
        int comp = i & 3;
        int o  = (slot & 3)*4 + (slot >> 2);
        int ci = c4*4 + comp;
        int r  = tp / 3, s5 = tp - r*3;
        wsx[i] = w1[((o*CIN + ci)*3 + r)*3 + s5];
    }
    // sim weights k=0..7 : ws8[(tp*16+o)*8 + k]
    for (int i = tid; i < 1152; i += 512) {
        int tp = i >> 7;
        int o  = (i >> 3) & 15;
        int k  = i & 7;
        int r  = tp / 3, s5 = tp - r*3;
        ws8[i] = w1[((o*CIN + 64 + k)*3 + r)*3 + s5];
    }
    // sim weight k=8 : ws1[tp*16+o]
    if (tid < 144) {
        int tp = tid >> 4, o = tid & 15;
        int r  = tp / 3, s5 = tp - r*3;
        ws1[tid] = w1[((o*CIN + 72)*3 + r)*3 + s5];
    }
    if (tid < 16) b1s[tid] = b1[tid];
    __syncthreads();

    // reciprocal norms for 400 halo pixels
    if (tid < N20) {
        const float4* tp4 = reinterpret_cast<const float4*>(xt + tid*PPX);
        float ss = 0.f;
#pragma unroll
        for (int c4 = 0; c4 < 16; c4++) {
            float4 v = tp4[c4];
            ss += v.x*v.x + v.y*v.y + v.z*v.z + v.w*v.w;
        }
        rn[tid] = 1.0f / (sqrtf(ss) + EPSV);
    }
    __syncthreads();

    const ulonglong2* xt2 = reinterpret_cast<const ulonglong2*>(xt);

    // cosine similarity on 18x18 halo
    if (tid < N18) {
        int row = tid / H18, col = tid - row*H18;
        int c20 = (row+1)*H20 + (col+1);
        ull acc[9];
#pragma unroll
        for (int k = 0; k < 9; k++) acc[k] = 0ULL;
#pragma unroll 4
        for (int c4 = 0; c4 < 16; c4++) {
            ulonglong2 cen = xt2[c20*PPX4 + c4];
#pragma unroll
            for (int dy = 0; dy < 3; dy++)
#pragma unroll
            for (int dx = 0; dx < 3; dx++) {
                ulonglong2 nb = xt2[(c20 + (dy-1)*H20 + (dx-1))*PPX4 + c4];
                fma2(acc[dy*3+dx], cen.x, nb.x);
                fma2(acc[dy*3+dx], cen.y, nb.y);
            }
        }
        float rc = rn[c20];
#pragma unroll
        for (int k = 0; k < 8; k++) {
            int dy = k / 3, dx = k - dy*3;
            st8[tid*8 + k] = red2(acc[k]) * rc * rn[c20 + (dy-1)*H20 + (dx-1)];
        }
        st1[tid] = red2(acc[8]) * rc * rn[c20 + H20 + 1];
    }
    __syncthreads();

    // main conv: thread = 2 pixels (rows py, py+8) x 4 out channels
    int og = tid & 3;
    int pg = tid >> 2;            // 0..127
    int py = pg >> 4;             // 0..7
    int px = pg & 15;             // 0..15

    ull   acc2[2][4];
    float accS[2][4];
#pragma unroll
    for (int i = 0; i < 2; i++)
#pragma unroll
        for (int j = 0; j < 4; j++) { acc2[i][j] = pk2(b1s[og*4 + j], 0.f); accS[i][j] = 0.f; }

    const ulonglong2* wsx2 = reinterpret_cast<const ulonglong2*>(wsx);

    int r = 0, s5 = 0;
#pragma unroll 1
    for (int tp = 0; tp < 9; tp++) {
        int h0 = (py + r + 1)*H20 + (px + s5 + 1);
        int h1 = h0 + 8*H20;
        int g0 = (py + r)*H18 + (px + s5);
        int g1 = g0 + 8*H18;
        const ulonglong2* wt = wsx2 + tp*256 + og;

#pragma unroll 4
        for (int c4 = 0; c4 < 16; c4++) {
            ulonglong2 f0 = xt2[h0*PPX4 + c4];
            ulonglong2 f1 = xt2[h1*PPX4 + c4];
            ulonglong2 wv[4];
#pragma unroll
            for (int j = 0; j < 4; j++) wv[j] = wt[c4*16 + j*4];
#pragma unroll
            for (int j = 0; j < 4; j++) {
                fma2(acc2[0][j], f0.x, wv[j].x);
                fma2(acc2[0][j], f0.y, wv[j].y);
                fma2(acc2[1][j], f1.x, wv[j].x);
                fma2(acc2[1][j], f1.y, wv[j].y);
            }
        }
        // sim channels k=0..7 (paired)
        const float* w8 = ws8 + (tp*16 + og*4)*8;
#pragma unroll
        for (int kk = 0; kk < 4; kk++) {
            ull wv2[4];
#pragma unroll
            for (int j = 0; j < 4; j++)
                wv2[j] = *reinterpret_cast<const ull*>(w8 + j*8 + 2*kk);
            ull fv0 = *reinterpret_cast<const ull*>(st8 + g0*8 + 2*kk);
            ull fv1 = *reinterpret_cast<const ull*>(st8 + g1*8 + 2*kk);
#pragma unroll
            for (int j = 0; j < 4; j++) {
                fma2(acc2[0][j], fv0, wv2[j]);
                fma2(acc2[1][j], fv1, wv2[j]);
            }
        }
        // sim channel k=8 (scalar)
        {
            float f0 = st1[g0], f1 = st1[g1];
            const float* w1r = ws1 + tp*16 + og*4;
#pragma unroll
            for (int j = 0; j < 4; j++) {
                accS[0][j] += f0 * w1r[j];
                accS[1][j] += f1 * w1r[j];
            }
        }
        s5++; if (s5 == 3) { s5 = 0; r++; }
    }

#pragma unroll
    for (int i = 0; i < 2; i++) {
        float a0 = red2(acc2[i][0]) + accS[i][0]; a0 = a0 >= 0.f ? a0 : 0.2f*a0;
        float a1 = red2(acc2[i][1]) + accS[i][1]; a1 = a1 >= 0.f ? a1 : 0.2f*a1;
        float a2 = red2(acc2[i][2]) + accS[i][2]; a2 = a2 >= 0.f ? a2 : 0.2f*a2;
        float a3 = red2(acc2[i][3]) + accS[i][3]; a3 = a3 >= 0.f ? a3 : 0.2f*a3;
        int pix = b*HW + (by + py + 8*i)*WW + (bx + px);
        reinterpret_cast<float4*>(g_hm + pix*CMID)[og] = make_float4(a0, a1, a2, a3);
    }
}

// ---------------------------------------------------------------------------
// K3: conv2 + tanh offset + warp-per-pixel coalesced gather + coalesced store
// ---------------------------------------------------------------------------
__global__ __launch_bounds__(256, 2) void k_sample(const float* __restrict__ w2,
                                                   const float* __restrict__ b2,
                                                   float* __restrict__ out) {
    extern __shared__ float sm[];
    float* sres = sm;                    // 256*66
    float* ht   = sm + 16896;            // 324*17
    float* ws2  = sm + 22404;            // 288
    float* swx  = sm + 22692;            // 256
    float* swy  = sm + 22948;            // 256
    int*   sxy  = (int*)(sm + 23204);    // 256
    float* b2s  = sm + 23460;            // 2

    int blk = blockIdx.x;
    int b   = blk >> 8;
    int tt  = blk & 255;
    int by  = (tt >> 4) * TS, bx = (tt & 15) * TS;
    int tid = threadIdx.x;
    const float* hb = g_hm + b*HW*CMID;

    for (int idx = tid; idx < N18*16; idx += 256) {
        int hp = idx >> 4, c = idx & 15;
        int hy = by + hp/H18 - 1, hx = bx + hp%H18 - 1;
        float v = 0.f;
        if ((unsigned)hy < HH && (unsigned)hx < WW)
            v = hb[(hy*WW + hx)*CMID + c];
        ht[hp*17 + c] = v;
    }
    for (int i = tid; i < 288; i += 256) {
        int tp = i >> 5, c = (i >> 1) & 15, o = i & 1;
        int r  = tp / 3, s5 = tp - r*3;
        ws2[i] = w2[((o*CMID + c)*3 + r)*3 + s5];
    }
    if (tid < 2) b2s[tid] = b2[tid];
    __syncthreads();

    {
        int ty = tid >> 4, tx = tid & 15;
        float a0 = b2s[0], a1 = b2s[1];
#pragma unroll
        for (int tp = 0; tp < 9; tp++) {
            int r = tp / 3, s5 = tp - r*3;
            const float* row = ht + ((ty + r)*H18 + (tx + s5))*17;
            const float* wr  = ws2 + tp*32;
#pragma unroll
            for (int c = 0; c < 16; c++) {
                float f = row[c];
                a0 += f * wr[c*2];
                a1 += f * wr[c*2 + 1];
            }
        }
        float offx = tanhf(a0) * 0.1f;
        float offy = tanhf(a1) * 0.1f;
        float ix = (float)(bx + tx) + offx * 127.5f;
        float iy = (float)(by + ty) + offy * 127.5f;
        ix = fminf(fmaxf(ix, 0.f), 255.f);
        iy = fminf(fmaxf(iy, 0.f), 255.f);
        float x0f = floorf(ix), y0f = floorf(iy);
        int x0 = (int)x0f, y0 = (int)y0f;
        sxy[tid] = x0 | (y0 << 16);
        swx[tid] = ix - x0f;
        swy[tid] = iy - y0f;
    }
    __syncthreads();

    {
        int wrp = tid >> 5, ln = tid & 31;
        const float2* xb2 = reinterpret_cast<const float2*>(g_xT + b*HW*CCH);
#pragma unroll 4
        for (int pi = 0; pi < 32; pi++) {
            int p  = wrp*32 + pi;
            int pk = sxy[p];
            int x0 = pk & 0xffff, y0 = pk >> 16;
            int x1 = min(x0 + 1, WW - 1), y1 = min(y0 + 1, HH - 1);
            float wx = swx[p], wy = swy[p];
            float2 v00 = xb2[(y0*WW + x0)*32 + ln];
            float2 v01 = xb2[(y0*WW + x1)*32 + ln];
            float2 v10 = xb2[(y1*WW + x0)*32 + ln];
            float2 v11 = xb2[(y1*WW + x1)*32 + ln];
            float omx = 1.f - wx, omy = 1.f - wy;
            float2 rr;
            rr.x = omy*(omx*v00.x + wx*v01.x) + wy*(omx*v10.x + wx*v11.x);
            rr.y = omy*(omx*v00.y + wx*v01.y) + wy*(omx*v10.y + wx*v11.y);
            *reinterpret_cast<float2*>(sres + p*66 + 2*ln) = rr;
        }
    }
    __syncthreads();

    {
        int ty = tid >> 4, tx = tid & 15;
        float* ob = out + b*CCH*HW + (by + ty)*WW + (bx + tx);
        const float* my = sres + tid*66;
#pragma unroll
        for (int c = 0; c < 64; c++) ob[c*HW] = my[c];
    }
}

// ---------------------------------------------------------------------------
extern "C" void kernel_launch(void* const* d_in, const int* in_sizes, int n_in,
                              void* d_out, int out_size) {
    const float* x  = (const float*)d_in[0];
    const float* w1 = (const float*)d_in[1];
    const float* b1 = (const float*)d_in[2];
    const float* w2 = (const float*)d_in[3];
    const float* b2 = (const float*)d_in[4];
    float* out = (float*)d_out;

    const int smem1 = SM1F * 4;     // 164,176 B -> 1 block/SM, 512 threads
    const int smem3 = 23462 * 4;    //  93,848 B -> 2 blocks/SM
    cudaFuncSetAttribute(k_conv1,  cudaFuncAttributeMaxDynamicSharedMemorySize, smem1);
    cudaFuncSetAttribute(k_sample, cudaFuncAttributeMaxDynamicSharedMemorySize, smem3);

    k_transpose<<<BATCH * (HW/64), 256>>>(x);
    k_conv1   <<<BATCH * 256, 512, smem1>>>(w1, b1);
    k_sample  <<<BATCH * 256, 256, smem3>>>(w2, b2, out);
    (void)in_sizes; (void)n_in; (void)out_size;
}

// round 11
// speedup vs baseline: 1.3453x; 1.3453x over previous
#include <cuda_runtime.h>
#include <math.h>

typedef unsigned long long ull;

#define BATCH 4
#define CCH   64
#define HH    256
#define WW    256
#define HW    65536
#define CMID  16
#define CIN   73
#define EPSV  1e-8f

// conv1 tile 16x16
#define TS   16
#define H20  20
#define H18  18
#define N20  400
#define N18  324
#define PPX  68
#define PPX4 17

// smem float offsets for k_conv1 (total 41044 floats = 164,176 B)
#define O_XT  0
#define O_RN  27200
#define O_ST8 27600
#define O_ST1 30192
#define O_WSX 30516
#define O_W8  39732
#define O_W1  40884
#define O_B1  41028
#define SM1F  41044

__device__ float g_xT[BATCH*HW*CCH];    // NHWC x
__device__ float g_hm[BATCH*HW*CMID];   // mid features NHWC16

// ---- packed f32x2 helpers ----
__device__ __forceinline__ void fma2(ull &d, ull a, ull b) {
    asm("fma.rn.f32x2 %0, %1, %2, %0;" : "+l"(d) : "l"(a), "l"(b));
}
__device__ __forceinline__ ull pk2(float lo, float hi) {
    ull r; asm("mov.b64 %0, {%1, %2};" : "=l"(r) : "f"(lo), "f"(hi)); return r;
}
__device__ __forceinline__ float red2(ull v) {
    float lo, hi; asm("mov.b64 {%0, %1}, %2;" : "=f"(lo), "=f"(hi) : "l"(v));
    return lo + hi;
}

// ---------------------------------------------------------------------------
// K1: NCHW -> NHWC transpose
// ---------------------------------------------------------------------------
__global__ __launch_bounds__(256) void k_transpose(const float* __restrict__ x) {
    __shared__ float s[64][65];
    int blk = blockIdx.x;
    int b   = blk >> 10;
    int p0  = (blk & 1023) << 6;
    int tid = threadIdx.x;
    const float* xb = x + b*CCH*HW;

    int pl = tid & 63;
    int c0 = tid >> 6;
#pragma unroll
    for (int i = 0; i < 16; i++) {
        int c = c0 + i*4;
        s[c][pl] = xb[c*HW + p0 + pl];
    }
    __syncthreads();

    int c4 = tid & 15;
    int pq = tid >> 4;
    float* out = g_xT + b*HW*CCH;
#pragma unroll
    for (int j = 0; j < 4; j++) {
        int p = pq + j*16;
        float4 v = make_float4(s[c4*4+0][p], s[c4*4+1][p], s[c4*4+2][p], s[c4*4+3][p]);
        reinterpret_cast<float4*>(out + (p0+p)*CCH)[c4] = v;
    }
}

// ---------------------------------------------------------------------------
// K2: fused cosine-sim + conv1 (73->16, 3x3) + leaky relu.
// 256 threads, 16x16 tile. Thread = 4 interleaved px (phase+4i) x 4 oc.
// ---------------------------------------------------------------------------
__global__ __launch_bounds__(256, 1) void k_conv1(const float* __restrict__ w1,
                                                  const float* __restrict__ b1) {
    extern __shared__ float sm[];
    float* xt  = sm + O_XT;    // 400*68 x halo (20x20)
    float* rn  = sm + O_RN;    // 400
    float* st8 = sm + O_ST8;   // 324*8  sim k=0..7 (pair-aligned)
    float* st1 = sm + O_ST1;   // 324    sim k=8
    float* wsx = sm + O_WSX;   // 9216 x-weights
    float* ws8 = sm + O_W8;    // 9*16*8 sim-weights k<8
    float* ws1 = sm + O_W1;    // 9*16   sim-weight  k=8
    float* b1s = sm + O_B1;    // 16

    int blk = blockIdx.x;
    int b   = blk >> 8;
    int tt  = blk & 255;
    int by  = (tt >> 4) * TS, bx = (tt & 15) * TS;
    int tid = threadIdx.x;
    const float* xb = g_xT + b*HW*CCH;

    // x halo (zero OOB)
    for (int idx = tid; idx < N20*16; idx += 256) {
        int hp = idx >> 4, c4 = idx & 15;
        int hy = by + hp/H20 - 2, hx = bx + hp%H20 - 2;
        float4 v = make_float4(0.f, 0.f, 0.f, 0.f);
        if ((unsigned)hy < HH && (unsigned)hx < WW)
            v = reinterpret_cast<const float4*>(xb + (hy*WW + hx)*CCH)[c4];
        reinterpret_cast<float4*>(xt + hp*PPX)[c4] = v;
    }
    // x weights: wsx[((tp*16+c4)*16 + slot)*4 + comp], slot=j*4+og, o=(slot&3)*4+(slot>>2)
    for (int i = tid; i < 9216; i += 256) {
        int tp   = i >> 10;
        int c4   = (i >> 6) & 15;
        int slot = (i >> 2) & 15;
        int comp = i & 3;
        int o  = (slot & 3)*4 + (slot >> 2);
        int ci = c4*4 + comp;
        int r  = tp / 3, s5 = tp - r*3;
        wsx[i] = w1[((o*CIN + ci)*3 + r)*3 + s5];
    }
    // sim weights k=0..7 : ws8[(tp*16+o)*8 + k]
    for (int i = tid; i < 1152; i += 256) {
        int tp = i >> 7;
        int o  = (i >> 3) & 15;
        int k  = i & 7;
        int r  = tp / 3, s5 = tp - r*3;
        ws8[i] = w1[((o*CIN + 64 + k)*3 + r)*3 + s5];
    }
    // sim weight k=8 : ws1[tp*16+o]
    if (tid < 144) {
        int tp = tid >> 4, o = tid & 15;
        int r  = tp / 3, s5 = tp - r*3;
        ws1[tid] = w1[((o*CIN + 72)*3 + r)*3 + s5];
    }
    if (tid < 16) b1s[tid] = b1[tid];
    __syncthreads();

    // reciprocal norms for 400 halo pixels
    for (int i = tid; i < N20; i += 256) {
        const float4* tp4 = reinterpret_cast<const float4*>(xt + i*PPX);
        float ss = 0.f;
#pragma unroll
        for (int c4 = 0; c4 < 16; c4++) {
            float4 v = tp4[c4];
            ss += v.x*v.x + v.y*v.y + v.z*v.z + v.w*v.w;
        }
        rn[i] = 1.0f / (sqrtf(ss) + EPSV);
    }
    __syncthreads();

    const ulonglong2* xt2 = reinterpret_cast<const ulonglong2*>(xt);

    // cosine similarity on 18x18 halo
    for (int hp = tid; hp < N18; hp += 256) {
        int row = hp / H18, col = hp - row*H18;
        int c20 = (row+1)*H20 + (col+1);
        ull acc[9];
#pragma unroll
        for (int k = 0; k < 9; k++) acc[k] = 0ULL;
#pragma unroll 4
        for (int c4 = 0; c4 < 16; c4++) {
            ulonglong2 cen = xt2[c20*PPX4 + c4];
#pragma unroll
            for (int dy = 0; dy < 3; dy++)
#pragma unroll
            for (int dx = 0; dx < 3; dx++) {
                ulonglong2 nb = xt2[(c20 + (dy-1)*H20 + (dx-1))*PPX4 + c4];
                fma2(acc[dy*3+dx], cen.x, nb.x);
                fma2(acc[dy*3+dx], cen.y, nb.y);
            }
        }
        float rc = rn[c20];
#pragma unroll
        for (int k = 0; k < 8; k++) {
            int dy = k / 3, dx = k - dy*3;
            st8[hp*8 + k] = red2(acc[k]) * rc * rn[c20 + (dy-1)*H20 + (dx-1)];
        }
        st1[hp] = red2(acc[8]) * rc * rn[c20 + H20 + 1];
    }
    __syncthreads();

    // main conv: thread = 4 interleaved pixels (phase + 4i) in one row x 4 oc
    int og    = tid & 3;
    int pg    = tid >> 2;         // 0..63
    int row   = pg >> 2;          // 0..15
    int phase = pg & 3;           // 0..3

    ull   acc2[4][4];
    float accS[4][4];
#pragma unroll
    for (int i = 0; i < 4; i++)
#pragma unroll
        for (int j = 0; j < 4; j++) { acc2[i][j] = pk2(b1s[og*4 + j], 0.f); accS[i][j] = 0.f; }

    const ulonglong2* wsx2 = reinterpret_cast<const ulonglong2*>(wsx);

    int r = 0, s5 = 0;
#pragma unroll 1
    for (int tp = 0; tp < 9; tp++) {
        int hbase = (row + r + 1)*H20 + (phase + s5 + 1);
        int gbase = (row + r)*H18 + (phase + s5);
        const ulonglong2* wt = wsx2 + tp*256 + og;

#pragma unroll 4
        for (int c4 = 0; c4 < 16; c4++) {
            ulonglong2 f[4];
#pragma unroll
            for (int i = 0; i < 4; i++) f[i] = xt2[(hbase + 4*i)*PPX4 + c4];
            ulonglong2 wv[4];
#pragma unroll
            for (int j = 0; j < 4; j++) wv[j] = wt[c4*16 + j*4];
#pragma unroll
            for (int i = 0; i < 4; i++)
#pragma unroll
                for (int j = 0; j < 4; j++) {
                    fma2(acc2[i][j], f[i].x, wv[j].x);
                    fma2(acc2[i][j], f[i].y, wv[j].y);
                }
        }
        // sim channels k=0..7 (paired)
        const float* w8 = ws8 + (tp*16 + og*4)*8;
#pragma unroll
        for (int kk = 0; kk < 4; kk++) {
            ull wv2[4];
#pragma unroll
            for (int j = 0; j < 4; j++)
                wv2[j] = *reinterpret_cast<const ull*>(w8 + j*8 + 2*kk);
#pragma unroll
            for (int i = 0; i < 4; i++) {
                ull fv = *reinterpret_cast<const ull*>(st8 + (gbase + 4*i)*8 + 2*kk);
#pragma unroll
                for (int j = 0; j < 4; j++) fma2(acc2[i][j], fv, wv2[j]);
            }
        }
        // sim channel k=8 (scalar)
        {
            const float* w1r = ws1 + tp*16 + og*4;
#pragma unroll
            for (int i = 0; i < 4; i++) {
                float fs = st1[gbase + 4*i];
#pragma unroll
                for (int j = 0; j < 4; j++) accS[i][j] += fs * w1r[j];
            }
        }
        s5++; if (s5 == 3) { s5 = 0; r++; }
    }

#pragma unroll
    for (int i = 0; i < 4; i++) {
        float a0 = red2(acc2[i][0]) + accS[i][0]; a0 = a0 >= 0.f ? a0 : 0.2f*a0;
        float a1 = red2(acc2[i][1]) + accS[i][1]; a1 = a1 >= 0.f ? a1 : 0.2f*a1;
        float a2 = red2(acc2[i][2]) + accS[i][2]; a2 = a2 >= 0.f ? a2 : 0.2f*a2;
        float a3 = red2(acc2[i][3]) + accS[i][3]; a3 = a3 >= 0.f ? a3 : 0.2f*a3;
        int pix = b*HW + (by + row)*WW + (bx + phase + 4*i);
        reinterpret_cast<float4*>(g_hm + pix*CMID)[og] = make_float4(a0, a1, a2, a3);
    }
}

// ---------------------------------------------------------------------------
// K3: conv2 + tanh offset + warp-per-pixel coalesced gather + coalesced store
// ---------------------------------------------------------------------------
__global__ __launch_bounds__(256, 2) void k_sample(const float* __restrict__ w2,
                                                   const float* __restrict__ b2,
                                                   float* __restrict__ out) {
    extern __shared__ float sm[];
    float* sres = sm;                    // 256*66
    float* ht   = sm + 16896;            // 324*17
    float* ws2  = sm + 22404;            // 288
    float* swx  = sm + 22692;            // 256
    float* swy  = sm + 22948;            // 256
    int*   sxy  = (int*)(sm + 23204);    // 256
    float* b2s  = sm + 23460;            // 2

    int blk = blockIdx.x;
    int b   = blk >> 8;
    int tt  = blk & 255;
    int by  = (tt >> 4) * TS, bx = (tt & 15) * TS;
    int tid = threadIdx.x;
    const float* hb = g_hm + b*HW*CMID;

    for (int idx = tid; idx < N18*16; idx += 256) {
        int hp = idx >> 4, c = idx & 15;
        int hy = by + hp/H18 - 1, hx = bx + hp%H18 - 1;
        float v = 0.f;
        if ((unsigned)hy < HH && (unsigned)hx < WW)
            v = hb[(hy*WW + hx)*CMID + c];
        ht[hp*17 + c] = v;
    }
    for (int i = tid; i < 288; i += 256) {
        int tp = i >> 5, c = (i >> 1) & 15, o = i & 1;
        int r  = tp / 3, s5 = tp - r*3;
        ws2[i] = w2[((o*CMID + c)*3 + r)*3 + s5];
    }
    if (tid < 2) b2s[tid] = b2[tid];
    __syncthreads();

    {
        int ty = tid >> 4, tx = tid & 15;
        float a0 = b2s[0], a1 = b2s[1];
#pragma unroll
        for (int tp = 0; tp < 9; tp++) {
            int r = tp / 3, s5 = tp - r*3;
            const float* row = ht + ((ty + r)*H18 + (tx + s5))*17;
            const float* wr  = ws2 + tp*32;
#pragma unroll
            for (int c = 0; c < 16; c++) {
                float f = row[c];
                a0 += f * wr[c*2];
                a1 += f * wr[c*2 + 1];
            }
        }
        float offx = tanhf(a0) * 0.1f;
        float offy = tanhf(a1) * 0.1f;
        float ix = (float)(bx + tx) + offx * 127.5f;
        float iy = (float)(by + ty) + offy * 127.5f;
        ix = fminf(fmaxf(ix, 0.f), 255.f);
        iy = fminf(fmaxf(iy, 0.f), 255.f);
        float x0f = floorf(ix), y0f = floorf(iy);
        int x0 = (int)x0f, y0 = (int)y0f;
        sxy[tid] = x0 | (y0 << 16);
        swx[tid] = ix - x0f;
        swy[tid] = iy - y0f;
    }
    __syncthreads();

    {
        int wrp = tid >> 5, ln = tid & 31;
        const float2* xb2 = reinterpret_cast<const float2*>(g_xT + b*HW*CCH);
#pragma unroll 4
        for (int pi = 0; pi < 32; pi++) {
            int p  = wrp*32 + pi;
            int pk = sxy[p];
            int x0 = pk & 0xffff, y0 = pk >> 16;
            int x1 = min(x0 + 1, WW - 1), y1 = min(y0 + 1, HH - 1);
            float wx = swx[p], wy = swy[p];
            float2 v00 = xb2[(y0*WW + x0)*32 + ln];
            float2 v01 = xb2[(y0*WW + x1)*32 + ln];
            float2 v10 = xb2[(y1*WW + x0)*32 + ln];
            float2 v11 = xb2[(y1*WW + x1)*32 + ln];
            float omx = 1.f - wx, omy = 1.f - wy;
            float2 rr;
            rr.x = omy*(omx*v00.x + wx*v01.x) + wy*(omx*v10.x + wx*v11.x);
            rr.y = omy*(omx*v00.y + wx*v01.y) + wy*(omx*v10.y + wx*v11.y);
            *reinterpret_cast<float2*>(sres + p*66 + 2*ln) = rr;
        }
    }
    __syncthreads();

    {
        int ty = tid >> 4, tx = tid & 15;
        float* ob = out + b*CCH*HW + (by + ty)*WW + (bx + tx);
        const float* my = sres + tid*66;
#pragma unroll
        for (int c = 0; c < 64; c++) ob[c*HW] = my[c];
    }
}

// ---------------------------------------------------------------------------
extern "C" void kernel_launch(void* const* d_in, const int* in_sizes, int n_in,
                              void* d_out, int out_size) {
    const float* x  = (const float*)d_in[0];
    const float* w1 = (const float*)d_in[1];
    const float* b1 = (const float*)d_in[2];
    const float* w2 = (const float*)d_in[3];
    const float* b2 = (const float*)d_in[4];
    float* out = (float*)d_out;

    const int smem1 = SM1F * 4;     // 164,176 B
    const int smem3 = 23462 * 4;    //  93,848 B -> 2 blocks/SM
    cudaFuncSetAttribute(k_conv1,  cudaFuncAttributeMaxDynamicSharedMemorySize, smem1);
    cudaFuncSetAttribute(k_sample, cudaFuncAttributeMaxDynamicSharedMemorySize, smem3);

    k_transpose<<<BATCH * (HW/64), 256>>>(x);
    k_conv1   <<<BATCH * 256, 256, smem1>>>(w1, b1);
    k_sample  <<<BATCH * 256, 256, smem3>>>(w2, b2, out);
    (void)in_sizes; (void)n_in; (void)out_size;
}